// round 10
// baseline (speedup 1.0000x reference)
#include <cuda_runtime.h>

#define NN 4096
#define EE 3
#define TT 5
#define DDIM 4
#define FF 64
#define HH 64
#define BB 2
#define PSTEPS 10
#define NC 8   // B*D columns of the skinny GEMM

// Persistent scratch (fully rewritten every launch -> deterministic)
__device__ __align__(16) float g_win[TT][NN][NC];       // [slot][n][b*4+d]
__device__ __align__(16) float g_PW [TT][EE][NN][NC];   // [slot][e][n][b*4+d] = A_e @ win_slot
__device__ __align__(16) float g_rowsum[EE][NN];
__device__ int g_mask[NN];

// ---- packed f32x2 helpers (sm_103a FFMA2 path, natural pairs: no MOV packing)
__device__ __forceinline__ void fma2(unsigned long long& d,
                                     unsigned long long a, unsigned long long b) {
  asm("fma.rn.f32x2 %0, %1, %2, %0;" : "+l"(d) : "l"(a), "l"(b));
}
__device__ __forceinline__ unsigned long long add2(unsigned long long a,
                                                   unsigned long long b) {
  unsigned long long r;
  asm("add.rn.f32x2 %0, %1, %2;" : "=l"(r) : "l"(a), "l"(b));
  return r;
}
__device__ __forceinline__ void upk2(unsigned long long v, float& lo, float& hi) {
  asm("mov.b64 {%0, %1}, %2;" : "=f"(lo), "=f"(hi) : "l"(v));
}
// 16B streaming load as two packed f32-pairs (evict-first; A is single-use)
__device__ __forceinline__ ulonglong2 ldcs_u64x2(const void* p) {
  ulonglong2 v;
  asm("ld.global.cs.v2.u64 {%0, %1}, [%2];" : "=l"(v.x), "=l"(v.y) : "l"(p));
  return v;
}

// ---------------------------------------------------------------------------
// Init: scatter time_segs [B,T,N,D] into window slots; zero mask.
// ---------------------------------------------------------------------------
__global__ void k_init(const float* __restrict__ ts) {
  int i = blockIdx.x * blockDim.x + threadIdx.x;
  if (i < NN) g_mask[i] = 0;
  if (i < BB * TT * NN * DDIM) {
    int d  = i & 3;
    int n  = (i >> 2) & (NN - 1);
    int bt = i >> 14;          // b*5 + t
    int t  = bt % 5;
    int b  = bt / 5;
    g_win[t][n][b * 4 + d] = ts[i];
  }
}

// ---------------------------------------------------------------------------
// Tall-skinny GEMM: g_PW[slot][e][n][c] = sum_m A[e][n][m] * g_win[slot][m][c]
// block = 128 (4 warps), warp owns 4 rows, lanes split m in 16B quads.
// X tile (1024 m x 8 c) staged column-major: XTs[c*1024 + m]. Adjacent m
// floats form natural f32x2 pairs for both A (from LDG.128) and X (LDS.128),
// so FFMA2 needs NO packing MOVs. Accumulators keep (even-m, odd-m) partial
// sums; halves merged once at the end (deterministic).
// grid = EE * 256. RS pass also emits exact row sums + column-any node mask.
// ---------------------------------------------------------------------------
template <bool RS>
__global__ void __launch_bounds__(128, 4) k_gemm(const float* __restrict__ A, int slot) {
  __shared__ __align__(16) float XTs[8 * 1024];   // 32 KB
  __shared__ unsigned s_any[4][256];

  const float* X = &g_win[slot][0][0];
  int e    = blockIdx.x >> 8;
  int tile = blockIdx.x & 255;
  int warp = threadIdx.x >> 5, lane = threadIdx.x & 31;
  int row0 = tile * 16 + warp * 4;

  const float* Ab0 = A + (size_t)e * NN * NN + (size_t)row0 * NN;
  const float* Ab1 = Ab0 + NN;
  const float* Ab2 = Ab1 + NN;
  const float* Ab3 = Ab2 + NN;

  unsigned long long acc2[4][8];
#pragma unroll
  for (int r = 0; r < 4; r++)
#pragma unroll
    for (int c = 0; c < 8; c++) acc2[r][c] = 0ull;
  float rs[4] = {0.f, 0.f, 0.f, 0.f};

  for (int t0 = 0; t0 < NN; t0 += 1024) {
    __syncthreads();
    // stage X tile transposed: XTs[c*1024 + m] = X[t0+m][c]
    const float4* X4 = (const float4*)(X + (size_t)t0 * NC);
    for (int i = threadIdx.x; i < 2048; i += 128) {
      float4 v = X4[i];
      int m = i >> 1, c0 = (i & 1) * 4;
      XTs[(c0 + 0) * 1024 + m] = v.x;
      XTs[(c0 + 1) * 1024 + m] = v.y;
      XTs[(c0 + 2) * 1024 + m] = v.z;
      XTs[(c0 + 3) * 1024 + m] = v.w;
    }
    __syncthreads();

#pragma unroll 2
    for (int it = 0; it < 8; it++) {
      int mq = it * 32 + lane;                  // 16B quad index within tile
      ulonglong2 av0 = ldcs_u64x2(Ab0 + t0 + 4 * mq);
      ulonglong2 av1 = ldcs_u64x2(Ab1 + t0 + 4 * mq);
      ulonglong2 av2 = ldcs_u64x2(Ab2 + t0 + 4 * mq);
      ulonglong2 av3 = ldcs_u64x2(Ab3 + t0 + 4 * mq);

      if (RS) {
        float f0, f1, f2, f3;
        upk2(av0.x, f0, f1); upk2(av0.y, f2, f3);
        float g0 = f0, g1 = f1, g2 = f2, g3 = f3;
        rs[0] += (f0 + f1) + (f2 + f3);
        upk2(av1.x, f0, f1); upk2(av1.y, f2, f3);
        rs[1] += (f0 + f1) + (f2 + f3);
        unsigned v = 0;
        if (g0 > 0.f || f0 > 0.f) v |= 0x1u;
        if (g1 > 0.f || f1 > 0.f) v |= 0x100u;
        if (g2 > 0.f || f2 > 0.f) v |= 0x10000u;
        if (g3 > 0.f || f3 > 0.f) v |= 0x1000000u;
        upk2(av2.x, f0, f1); upk2(av2.y, f2, f3);
        rs[2] += (f0 + f1) + (f2 + f3);
        if (f0 > 0.f) v |= 0x1u;
        if (f1 > 0.f) v |= 0x100u;
        if (f2 > 0.f) v |= 0x10000u;
        if (f3 > 0.f) v |= 0x1000000u;
        upk2(av3.x, f0, f1); upk2(av3.y, f2, f3);
        rs[3] += (f0 + f1) + (f2 + f3);
        if (f0 > 0.f) v |= 0x1u;
        if (f1 > 0.f) v |= 0x100u;
        if (f2 > 0.f) v |= 0x10000u;
        if (f3 > 0.f) v |= 0x1000000u;
        s_any[warp][mq] = v;     // every warp covers every mq of the tile
      }

#pragma unroll
      for (int c = 0; c < 8; c++) {
        ulonglong2 q = *(const ulonglong2*)&XTs[c * 1024 + 4 * mq];
        fma2(acc2[0][c], av0.x, q.x); fma2(acc2[0][c], av0.y, q.y);
        fma2(acc2[1][c], av1.x, q.x); fma2(acc2[1][c], av1.y, q.y);
        fma2(acc2[2][c], av2.x, q.x); fma2(acc2[2][c], av2.y, q.y);
        fma2(acc2[3][c], av3.x, q.x); fma2(acc2[3][c], av3.y, q.y);
      }
    }

    if (RS) {
      __syncthreads();
      for (int i = threadIdx.x; i < 256; i += 128) {
        unsigned v = s_any[0][i] | s_any[1][i] | s_any[2][i] | s_any[3][i];
        int mg = t0 + i * 4;
        if (v & 0x1u)        g_mask[mg + 0] = 1;   // same-value store: race-safe
        if (v & 0x100u)      g_mask[mg + 1] = 1;
        if (v & 0x10000u)    g_mask[mg + 2] = 1;
        if (v & 0x1000000u)  g_mask[mg + 3] = 1;
      }
    }
  }

  // butterfly reduction across lanes (packed), then merge even/odd halves
#pragma unroll
  for (int r = 0; r < 4; r++)
#pragma unroll
    for (int c = 0; c < 8; c++) {
      unsigned long long v = acc2[r][c];
#pragma unroll
      for (int off = 16; off; off >>= 1)
        v = add2(v, __shfl_xor_sync(0xffffffffu, v, off));
      acc2[r][c] = v;
    }
  if (RS) {
#pragma unroll
    for (int r = 0; r < 4; r++) {
      float v = rs[r];
#pragma unroll
      for (int off = 16; off; off >>= 1) v += __shfl_xor_sync(0xffffffffu, v, off);
      rs[r] = v;
    }
  }

  if (lane == 0) {
#pragma unroll
    for (int r = 0; r < 4; r++) {
      float o[8];
#pragma unroll
      for (int c = 0; c < 8; c++) {
        float lo, hi;
        upk2(acc2[r][c], lo, hi);
        o[c] = lo + hi;
      }
      float4* dst = (float4*)&g_PW[slot][e][row0 + r][0];
      dst[0] = make_float4(o[0], o[1], o[2], o[3]);
      dst[1] = make_float4(o[4], o[5], o[6], o[7]);
      if (RS) g_rowsum[e][row0 + r] = rs[r];
    }
  }
}

// ---------------------------------------------------------------------------
// Fused per-node step. block = 128 (4 warps), each warp handles 4 (b,n)
// instances. Lane owns channel pair {2l, 2l+1} -> float2 weight loads.
// grid = 8192/16 = 512.
// ---------------------------------------------------------------------------
__global__ void __launch_bounds__(128) k_step(
    const float* __restrict__ conv_w, const float* __restrict__ conv_b,
    const float* __restrict__ enc_w1, const float* __restrict__ enc_w2,
    const float* __restrict__ enc_b,  const float* __restrict__ dec_w,
    const float* __restrict__ dec_b,  const float* __restrict__ out_w,
    const float* __restrict__ out_b,  float* __restrict__ dout, int s)
{
  __shared__ __align__(16) float s_win[4][4][20];
  __shared__ __align__(16) float s_pw [4][4][60];
  __shared__ __align__(16) float s_cond[4][4][64];
  __shared__ __align__(16) float s_agg [4][4][192];
  __shared__ __align__(16) float s_enc [4][4][64];

  int warp = threadIdx.x >> 5, lane = threadIdx.x & 31;
  int l2 = lane * 2;
  int base = blockIdx.x * 16 + warp * 4;

  // ---- stage window + PW values for this warp's 4 instances ----
  for (int j = lane; j < 80; j += 32) {
    int li = j / 20, k = j % 20;
    int inst = base + li;
    int b = inst >> 12, n = inst & (NN - 1);
    if (k < 5) {
      int slotv = (s + k) % 5;
      float4 v = *(const float4*)&g_win[slotv][n][b * 4];
      *(float4*)&s_win[warp][li][k * 4] = v;
    } else {
      int k2 = k - 5, e = k2 / 5, t = k2 % 5;
      int slotv = (s + t) % 5;
      float4 v = *(const float4*)&g_PW[slotv][e][n][b * 4];
      *(float4*)&s_pw[warp][li][e * 20 + t * 4] = v;
    }
  }
  __syncwarp();

  int nn[4];
#pragma unroll
  for (int i = 0; i < 4; i++) nn[i] = (base + i) & (NN - 1);

  // ---- cond + agg (20 -> 64 contractions) ----
  float2 cb = *(const float2*)&conv_b[l2];
  float cond[4][2], agg[4][3][2];
#pragma unroll
  for (int i = 0; i < 4; i++) {
    cond[i][0] = cb.x; cond[i][1] = cb.y;
#pragma unroll
    for (int e = 0; e < 3; e++) {
      float r = g_rowsum[e][nn[i]];
      agg[i][e][0] = r * cb.x; agg[i][e][1] = r * cb.y;
    }
  }
  for (int td = 0; td < 20; td++) {
    float2 cw = *(const float2*)&conv_w[td * 64 + l2];
#pragma unroll
    for (int i = 0; i < 4; i++) {
      float w = s_win[warp][i][td];
      cond[i][0] += w * cw.x; cond[i][1] += w * cw.y;
#pragma unroll
      for (int e = 0; e < 3; e++) {
        float a = s_pw[warp][i][e * 20 + td];
        agg[i][e][0] += a * cw.x; agg[i][e][1] += a * cw.y;
      }
    }
  }
#pragma unroll
  for (int i = 0; i < 4; i++) {
    *(float2*)&s_cond[warp][i][l2] = make_float2(cond[i][0], cond[i][1]);
#pragma unroll
    for (int e = 0; e < 3; e++)
      *(float2*)&s_agg[warp][i][e * 64 + l2] = make_float2(agg[i][e][0], agg[i][e][1]);
  }
  __syncwarp();

  // ---- per-edge-type GCSConv + tanh stack ----
  float encs[4][2];
#pragma unroll
  for (int i = 0; i < 4; i++) { encs[i][0] = 0.f; encs[i][1] = 0.f; }
  for (int e = 0; e < 3; e++) {
    float acc[4][2];
    float2 eb = *(const float2*)&enc_b[e * 64 + l2];
#pragma unroll
    for (int i = 0; i < 4; i++) { acc[i][0] = eb.x; acc[i][1] = eb.y; }
    for (int f = 0; f < 64; f++) {
      int wi = (e * 64 + f) * 64 + l2;
      float2 w1 = *(const float2*)&enc_w1[wi];
      float2 w2 = *(const float2*)&enc_w2[wi];
#pragma unroll
      for (int i = 0; i < 4; i++) {
        float a = s_agg[warp][i][e * 64 + f];
        float c = s_cond[warp][i][f];
        acc[i][0] += a * w1.x + c * w2.x;
        acc[i][1] += a * w1.y + c * w2.y;
      }
    }
#pragma unroll
    for (int i = 0; i < 4; i++) {
      encs[i][0] += tanhf(acc[i][0]);
      encs[i][1] += tanhf(acc[i][1]);
    }
  }
#pragma unroll
  for (int i = 0; i < 4; i++) {
    float mk = g_mask[nn[i]] ? 1.0f : 0.0f;
    *(float2*)&s_enc[warp][i][l2] =
        make_float2(tanhf(encs[i][0]) * mk, tanhf(encs[i][1]) * mk);
  }
  __syncwarp();

  // ---- decoder: relu([cond, enc] @ dec_w + dec_b) ----
  float hh[4][2];
  float2 db = *(const float2*)&dec_b[l2];
#pragma unroll
  for (int i = 0; i < 4; i++) { hh[i][0] = db.x; hh[i][1] = db.y; }
  for (int k = 0; k < 64; k++) {
    float2 dw = *(const float2*)&dec_w[k * 64 + l2];
#pragma unroll
    for (int i = 0; i < 4; i++) {
      float x = s_cond[warp][i][k];
      hh[i][0] += x * dw.x; hh[i][1] += x * dw.y;
    }
  }
  for (int k = 0; k < 64; k++) {
    float2 dw = *(const float2*)&dec_w[(64 + k) * 64 + l2];
#pragma unroll
    for (int i = 0; i < 4; i++) {
      float x = s_enc[warp][i][k];
      hh[i][0] += x * dw.x; hh[i][1] += x * dw.y;
    }
  }
#pragma unroll
  for (int i = 0; i < 4; i++) {
    hh[i][0] = fmaxf(hh[i][0], 0.f);
    hh[i][1] = fmaxf(hh[i][1], 0.f);
  }

  // ---- output projection + residual + window update ----
  float4 owa = *(const float4*)&out_w[l2 * 4];
  float4 owb = *(const float4*)&out_w[(l2 + 1) * 4];
  float ob0 = out_b[0], ob1 = out_b[1], ob2 = out_b[2], ob3 = out_b[3];
  int slot_new = s % 5;
#pragma unroll
  for (int i = 0; i < 4; i++) {
    float p0 = hh[i][0] * owa.x + hh[i][1] * owb.x;
    float p1 = hh[i][0] * owa.y + hh[i][1] * owb.y;
    float p2 = hh[i][0] * owa.z + hh[i][1] * owb.z;
    float p3 = hh[i][0] * owa.w + hh[i][1] * owb.w;
#pragma unroll
    for (int off = 16; off; off >>= 1) {
      p0 += __shfl_xor_sync(0xffffffffu, p0, off);
      p1 += __shfl_xor_sync(0xffffffffu, p1, off);
      p2 += __shfl_xor_sync(0xffffffffu, p2, off);
      p3 += __shfl_xor_sync(0xffffffffu, p3, off);
    }
    if (lane == 0) {
      int inst = base + i;
      int b = inst >> 12, n = inst & (NN - 1);
      float4 o;
      o.x = s_win[warp][i][16] + tanhf(p0 + ob0);
      o.y = s_win[warp][i][17] + tanhf(p1 + ob1);
      o.z = s_win[warp][i][18] + tanhf(p2 + ob2);
      o.w = s_win[warp][i][19] + tanhf(p3 + ob3);
      *(float4*)&g_win[slot_new][n][b * 4] = o;
      *(float4*)&dout[(size_t)((b * PSTEPS + s) * NN + n) * 4] = o;
    }
  }
}

// ---------------------------------------------------------------------------
extern "C" void kernel_launch(void* const* d_in, const int* in_sizes, int n_in,
                              void* d_out, int out_size) {
  const float* ts     = (const float*)d_in[0];
  const float* A      = (const float*)d_in[1];
  const float* conv_w = (const float*)d_in[2];
  const float* conv_b = (const float*)d_in[3];
  const float* enc_w1 = (const float*)d_in[4];
  const float* enc_w2 = (const float*)d_in[5];
  const float* enc_b  = (const float*)d_in[6];
  const float* dec_w  = (const float*)d_in[7];
  const float* dec_b  = (const float*)d_in[8];
  const float* out_w  = (const float*)d_in[9];
  const float* out_b  = (const float*)d_in[10];
  float* out = (float*)d_out;

  k_init<<<640, 256>>>(ts);
  k_gemm<true ><<<EE * 256, 128>>>(A, 0);   // slot 0 + rowsum + node mask
  for (int t = 1; t < TT; t++)
    k_gemm<false><<<EE * 256, 128>>>(A, t);

  for (int s = 0; s < PSTEPS; s++) {
    k_step<<<512, 128>>>(conv_w, conv_b, enc_w1, enc_w2, enc_b,
                         dec_w, dec_b, out_w, out_b, out, s);
    if (s < PSTEPS - 1)
      k_gemm<false><<<EE * 256, 128>>>(A, s % 5);
  }
}

// round 12
// speedup vs baseline: 1.2719x; 1.2719x over previous
#include <cuda_runtime.h>

#define NN 4096
#define EE 3
#define TT 5
#define DDIM 4
#define FF 64
#define HH 64
#define BB 2
#define PSTEPS 10
#define NC 8   // B*D columns of the skinny GEMM

// Persistent scratch (fully rewritten every launch -> deterministic)
__device__ __align__(16) float g_win[TT][NN][NC];          // [slot][n][b*4+d]
__device__ __align__(16) float g_PWp[2][TT][EE][NN][NC];   // [half][slot][e][n][c] partial sums
__device__ __align__(16) float g_rsp[2][EE][NN];           // partial row sums
__device__ int g_mask[NN];

// ---------------------------------------------------------------------------
// Init: scatter time_segs [B,T,N,D] into window slots; zero mask.
// ---------------------------------------------------------------------------
__global__ void k_init(const float* __restrict__ ts) {
  int i = blockIdx.x * blockDim.x + threadIdx.x;
  if (i < NN) g_mask[i] = 0;
  if (i < BB * TT * NN * DDIM) {
    int d  = i & 3;
    int n  = (i >> 2) & (NN - 1);
    int bt = i >> 14;          // b*5 + t
    int t  = bt % 5;
    int b  = bt / 5;
    g_win[t][n][b * 4 + d] = ts[i];
  }
}

// ---------------------------------------------------------------------------
// Tall-skinny GEMM, m-SPLIT across 2 block-halves for occupancy:
//   g_PWp[half][slot][e][n][c] = sum_{m in half} A[e][n][m] * g_win[slot][m][c]
// block = 128 (4 warps), warp owns 4 rows, lanes split m in float4 quads.
// X tile = 512 m staged transposed in smem (16 KB -> many blocks/SM).
// grid = EE * 512 (e * 2-halves * 256 row-tiles).
// RS pass also emits per-half row sums + column-any node mask.
// ---------------------------------------------------------------------------
template <bool RS>
__global__ void __launch_bounds__(128, 8) k_gemm(const float* __restrict__ A, int slot) {
  __shared__ __align__(16) float XTs[8 * 512];   // 16 KB, col-major tile
  __shared__ unsigned s_any[4][128];

  const float* X = &g_win[slot][0][0];
  int e     = blockIdx.x / 512;
  int rest  = blockIdx.x & 511;
  int half  = rest >> 8;
  int tile  = rest & 255;
  int mbase = half * 2048;
  int warp  = threadIdx.x >> 5, lane = threadIdx.x & 31;
  int row0  = tile * 16 + warp * 4;

  const float* Ab0 = A + (size_t)e * NN * NN + (size_t)row0 * NN + mbase;
  const float* Ab1 = Ab0 + NN;
  const float* Ab2 = Ab1 + NN;
  const float* Ab3 = Ab2 + NN;

  float acc[4][8];
#pragma unroll
  for (int r = 0; r < 4; r++)
#pragma unroll
    for (int c = 0; c < 8; c++) acc[r][c] = 0.f;
  float rs[4] = {0.f, 0.f, 0.f, 0.f};

  for (int t0 = 0; t0 < 2048; t0 += 512) {
    __syncthreads();
    // stage X tile transposed: XTs[c*512 + m] = X[mbase+t0+m][c]
    const float4* X4 = (const float4*)(X + (size_t)(mbase + t0) * NC);
    for (int i = threadIdx.x; i < 1024; i += 128) {
      float4 v = X4[i];
      int m = i >> 1, c0 = (i & 1) * 4;
      XTs[(c0 + 0) * 512 + m] = v.x;
      XTs[(c0 + 1) * 512 + m] = v.y;
      XTs[(c0 + 2) * 512 + m] = v.z;
      XTs[(c0 + 3) * 512 + m] = v.w;
    }
    __syncthreads();

    const float4* A0 = (const float4*)(Ab0 + t0);
    const float4* A1 = (const float4*)(Ab1 + t0);
    const float4* A2 = (const float4*)(Ab2 + t0);
    const float4* A3 = (const float4*)(Ab3 + t0);

#pragma unroll 2
    for (int it = 0; it < 4; it++) {
      int mq = it * 32 + lane;
      float4 a0 = __ldcs(A0 + mq);
      float4 a1 = __ldcs(A1 + mq);
      float4 a2 = __ldcs(A2 + mq);
      float4 a3 = __ldcs(A3 + mq);

      if (RS) {
        rs[0] += (a0.x + a0.y) + (a0.z + a0.w);
        rs[1] += (a1.x + a1.y) + (a1.z + a1.w);
        rs[2] += (a2.x + a2.y) + (a2.z + a2.w);
        rs[3] += (a3.x + a3.y) + (a3.z + a3.w);
        unsigned v = 0;
        if (a0.x > 0.f || a1.x > 0.f || a2.x > 0.f || a3.x > 0.f) v |= 0x1u;
        if (a0.y > 0.f || a1.y > 0.f || a2.y > 0.f || a3.y > 0.f) v |= 0x100u;
        if (a0.z > 0.f || a1.z > 0.f || a2.z > 0.f || a3.z > 0.f) v |= 0x10000u;
        if (a0.w > 0.f || a1.w > 0.f || a2.w > 0.f || a3.w > 0.f) v |= 0x1000000u;
        s_any[warp][mq] = v;     // every warp covers every mq of the tile
      }

#pragma unroll
      for (int c = 0; c < 8; c++) {
        const float4 x = *(const float4*)&XTs[c * 512 + 4 * mq];
        acc[0][c] = fmaf(a0.w, x.w, fmaf(a0.z, x.z, fmaf(a0.y, x.y, fmaf(a0.x, x.x, acc[0][c]))));
        acc[1][c] = fmaf(a1.w, x.w, fmaf(a1.z, x.z, fmaf(a1.y, x.y, fmaf(a1.x, x.x, acc[1][c]))));
        acc[2][c] = fmaf(a2.w, x.w, fmaf(a2.z, x.z, fmaf(a2.y, x.y, fmaf(a2.x, x.x, acc[2][c]))));
        acc[3][c] = fmaf(a3.w, x.w, fmaf(a3.z, x.z, fmaf(a3.y, x.y, fmaf(a3.x, x.x, acc[3][c]))));
      }
    }

    if (RS) {
      __syncthreads();
      for (int i = threadIdx.x; i < 128; i += 128) {
        unsigned v = s_any[0][i] | s_any[1][i] | s_any[2][i] | s_any[3][i];
        int mg = mbase + t0 + i * 4;
        if (v & 0x1u)        g_mask[mg + 0] = 1;   // same-value store: race-safe
        if (v & 0x100u)      g_mask[mg + 1] = 1;
        if (v & 0x10000u)    g_mask[mg + 2] = 1;
        if (v & 0x1000000u)  g_mask[mg + 3] = 1;
      }
    }
  }

  // deterministic butterfly reduction across lanes
#pragma unroll
  for (int r = 0; r < 4; r++) {
#pragma unroll
    for (int c = 0; c < 8; c++) {
      float v = acc[r][c];
#pragma unroll
      for (int off = 16; off; off >>= 1) v += __shfl_xor_sync(0xffffffffu, v, off);
      acc[r][c] = v;
    }
    if (RS) {
      float v = rs[r];
#pragma unroll
      for (int off = 16; off; off >>= 1) v += __shfl_xor_sync(0xffffffffu, v, off);
      rs[r] = v;
    }
  }
  if (lane == 0) {
#pragma unroll
    for (int r = 0; r < 4; r++) {
      float4* dst = (float4*)&g_PWp[half][slot][e][row0 + r][0];
      dst[0] = make_float4(acc[r][0], acc[r][1], acc[r][2], acc[r][3]);
      dst[1] = make_float4(acc[r][4], acc[r][5], acc[r][6], acc[r][7]);
      if (RS) g_rsp[half][e][row0 + r] = rs[r];
    }
  }
}

// ---------------------------------------------------------------------------
// Fused per-node step. block = 128 (4 warps), each warp handles 4 (b,n)
// instances; lane owns channels {2l, 2l+1}. Encoder weights staged in smem
// in 32-f chunks (interleaved float4: w1.lo, w1.hi, w2.lo, w2.hi) so the
// inner loop is 1 LDS.128 + broadcasts + FMAs. grid = 512.
// ---------------------------------------------------------------------------
__global__ void __launch_bounds__(128) k_step(
    const float* __restrict__ conv_w, const float* __restrict__ conv_b,
    const float* __restrict__ enc_w1, const float* __restrict__ enc_w2,
    const float* __restrict__ enc_b,  const float* __restrict__ dec_w,
    const float* __restrict__ dec_b,  const float* __restrict__ out_w,
    const float* __restrict__ out_b,  float* __restrict__ dout, int s)
{
  __shared__ __align__(16) float s_win[4][4][20];
  __shared__ __align__(16) float s_pw [4][4][60];
  __shared__ __align__(16) float s_cond[4][4][64];
  __shared__ __align__(16) float s_agg [4][4][192];
  __shared__ __align__(16) float s_enc [4][4][64];
  __shared__ __align__(16) float4 s_ew[32][32];   // 16 KB chunk of enc weights

  int warp = threadIdx.x >> 5, lane = threadIdx.x & 31;
  int l2 = lane * 2;
  int base = blockIdx.x * 16 + warp * 4;

  // ---- stage window + PW (sum of m-halves) for this warp's 4 instances ----
  for (int j = lane; j < 80; j += 32) {
    int li = j / 20, k = j % 20;
    int inst = base + li;
    int b = inst >> 12, n = inst & (NN - 1);
    if (k < 5) {
      int slotv = (s + k) % 5;
      float4 v = *(const float4*)&g_win[slotv][n][b * 4];
      *(float4*)&s_win[warp][li][k * 4] = v;
    } else {
      int k2 = k - 5, e = k2 / 5, t = k2 % 5;
      int slotv = (s + t) % 5;
      float4 v0 = *(const float4*)&g_PWp[0][slotv][e][n][b * 4];
      float4 v1 = *(const float4*)&g_PWp[1][slotv][e][n][b * 4];
      *(float4*)&s_pw[warp][li][e * 20 + t * 4] =
          make_float4(v0.x + v1.x, v0.y + v1.y, v0.z + v1.z, v0.w + v1.w);
    }
  }
  __syncwarp();

  int nn[4];
#pragma unroll
  for (int i = 0; i < 4; i++) nn[i] = (base + i) & (NN - 1);

  // ---- cond + agg (20 -> 64 contractions) ----
  float2 cb = *(const float2*)&conv_b[l2];
  float cond[4][2], agg[4][3][2];
#pragma unroll
  for (int i = 0; i < 4; i++) {
    cond[i][0] = cb.x; cond[i][1] = cb.y;
#pragma unroll
    for (int e = 0; e < 3; e++) {
      float r = g_rsp[0][e][nn[i]] + g_rsp[1][e][nn[i]];
      agg[i][e][0] = r * cb.x; agg[i][e][1] = r * cb.y;
    }
  }
  for (int td = 0; td < 20; td++) {
    float2 cw = *(const float2*)&conv_w[td * 64 + l2];
#pragma unroll
    for (int i = 0; i < 4; i++) {
      float w = s_win[warp][i][td];
      cond[i][0] += w * cw.x; cond[i][1] += w * cw.y;
#pragma unroll
      for (int e = 0; e < 3; e++) {
        float a = s_pw[warp][i][e * 20 + td];
        agg[i][e][0] += a * cw.x; agg[i][e][1] += a * cw.y;
      }
    }
  }
#pragma unroll
  for (int i = 0; i < 4; i++) {
    *(float2*)&s_cond[warp][i][l2] = make_float2(cond[i][0], cond[i][1]);
#pragma unroll
    for (int e = 0; e < 3; e++)
      *(float2*)&s_agg[warp][i][e * 64 + l2] = make_float2(agg[i][e][0], agg[i][e][1]);
  }
  __syncthreads();

  // ---- per-edge-type GCSConv + tanh stack (smem-staged weights) ----
  float encs[4][2];
#pragma unroll
  for (int i = 0; i < 4; i++) { encs[i][0] = 0.f; encs[i][1] = 0.f; }
  for (int e = 0; e < 3; e++) {
    float acc[4][2];
    float2 eb = *(const float2*)&enc_b[e * 64 + l2];
#pragma unroll
    for (int i = 0; i < 4; i++) { acc[i][0] = eb.x; acc[i][1] = eb.y; }
    for (int fc = 0; fc < 2; fc++) {
      // stage 32 rows of enc_w1/enc_w2, interleaved per lane-pair
      for (int i2 = threadIdx.x; i2 < 1024; i2 += 128) {
        int f = i2 >> 5, p = i2 & 31;
        int row = (e * 64 + fc * 32 + f) * 64 + 2 * p;
        float2 w1 = *(const float2*)&enc_w1[row];
        float2 w2 = *(const float2*)&enc_w2[row];
        s_ew[f][p] = make_float4(w1.x, w1.y, w2.x, w2.y);
      }
      __syncthreads();
      int fg0 = e * 64 + fc * 32;
#pragma unroll 8
      for (int f = 0; f < 32; f++) {
        float4 w = s_ew[f][lane];
#pragma unroll
        for (int i = 0; i < 4; i++) {
          float a = s_agg[warp][i][fg0 + f - e * 64 + e * 64];  // = s_agg[warp][i][fg0+f]
          float c = s_cond[warp][i][fc * 32 + f];
          a = s_agg[warp][i][fg0 + f];
          acc[i][0] += a * w.x + c * w.z;
          acc[i][1] += a * w.y + c * w.w;
        }
      }
      __syncthreads();
    }
#pragma unroll
    for (int i = 0; i < 4; i++) {
      encs[i][0] += tanhf(acc[i][0]);
      encs[i][1] += tanhf(acc[i][1]);
    }
  }
#pragma unroll
  for (int i = 0; i < 4; i++) {
    float mk = g_mask[nn[i]] ? 1.0f : 0.0f;
    *(float2*)&s_enc[warp][i][l2] =
        make_float2(tanhf(encs[i][0]) * mk, tanhf(encs[i][1]) * mk);
  }
  __syncwarp();

  // ---- decoder: relu([cond, enc] @ dec_w + dec_b) ----
  float hh[4][2];
  float2 db = *(const float2*)&dec_b[l2];
#pragma unroll
  for (int i = 0; i < 4; i++) { hh[i][0] = db.x; hh[i][1] = db.y; }
  for (int k = 0; k < 64; k++) {
    float2 dw = *(const float2*)&dec_w[k * 64 + l2];
#pragma unroll
    for (int i = 0; i < 4; i++) {
      float x = s_cond[warp][i][k];
      hh[i][0] += x * dw.x; hh[i][1] += x * dw.y;
    }
  }
  for (int k = 0; k < 64; k++) {
    float2 dw = *(const float2*)&dec_w[(64 + k) * 64 + l2];
#pragma unroll
    for (int i = 0; i < 4; i++) {
      float x = s_enc[warp][i][k];
      hh[i][0] += x * dw.x; hh[i][1] += x * dw.y;
    }
  }
#pragma unroll
  for (int i = 0; i < 4; i++) {
    hh[i][0] = fmaxf(hh[i][0], 0.f);
    hh[i][1] = fmaxf(hh[i][1], 0.f);
  }

  // ---- output projection + residual + window update ----
  float4 owa = *(const float4*)&out_w[l2 * 4];
  float4 owb = *(const float4*)&out_w[(l2 + 1) * 4];
  float ob0 = out_b[0], ob1 = out_b[1], ob2 = out_b[2], ob3 = out_b[3];
  int slot_new = s % 5;
#pragma unroll
  for (int i = 0; i < 4; i++) {
    float p0 = hh[i][0] * owa.x + hh[i][1] * owb.x;
    float p1 = hh[i][0] * owa.y + hh[i][1] * owb.y;
    float p2 = hh[i][0] * owa.z + hh[i][1] * owb.z;
    float p3 = hh[i][0] * owa.w + hh[i][1] * owb.w;
#pragma unroll
    for (int off = 16; off; off >>= 1) {
      p0 += __shfl_xor_sync(0xffffffffu, p0, off);
      p1 += __shfl_xor_sync(0xffffffffu, p1, off);
      p2 += __shfl_xor_sync(0xffffffffu, p2, off);
      p3 += __shfl_xor_sync(0xffffffffu, p3, off);
    }
    if (lane == 0) {
      int inst = base + i;
      int b = inst >> 12, n = inst & (NN - 1);
      float4 o;
      o.x = s_win[warp][i][16] + tanhf(p0 + ob0);
      o.y = s_win[warp][i][17] + tanhf(p1 + ob1);
      o.z = s_win[warp][i][18] + tanhf(p2 + ob2);
      o.w = s_win[warp][i][19] + tanhf(p3 + ob3);
      *(float4*)&g_win[slot_new][n][b * 4] = o;
      *(float4*)&dout[(size_t)((b * PSTEPS + s) * NN + n) * 4] = o;
    }
  }
}

// ---------------------------------------------------------------------------
extern "C" void kernel_launch(void* const* d_in, const int* in_sizes, int n_in,
                              void* d_out, int out_size) {
  const float* ts     = (const float*)d_in[0];
  const float* A      = (const float*)d_in[1];
  const float* conv_w = (const float*)d_in[2];
  const float* conv_b = (const float*)d_in[3];
  const float* enc_w1 = (const float*)d_in[4];
  const float* enc_w2 = (const float*)d_in[5];
  const float* enc_b  = (const float*)d_in[6];
  const float* dec_w  = (const float*)d_in[7];
  const float* dec_b  = (const float*)d_in[8];
  const float* out_w  = (const float*)d_in[9];
  const float* out_b  = (const float*)d_in[10];
  float* out = (float*)d_out;

  k_init<<<640, 256>>>(ts);
  k_gemm<true ><<<EE * 512, 128>>>(A, 0);   // slot 0 + rowsums + node mask
  for (int t = 1; t < TT; t++)
    k_gemm<false><<<EE * 512, 128>>>(A, t);

  for (int s = 0; s < PSTEPS; s++) {
    k_step<<<512, 128>>>(conv_w, conv_b, enc_w1, enc_w2, enc_b,
                         dec_w, dec_b, out_w, out_b, out, s);
    if (s < PSTEPS - 1)
      k_gemm<false><<<EE * 512, 128>>>(A, s % 5);
  }
}

// round 14
// speedup vs baseline: 1.4988x; 1.1784x over previous
#include <cuda_runtime.h>
#include <cuda_fp16.h>

#define NN 4096
#define EE 3
#define TT 5
#define DDIM 4
#define FF 64
#define HH 64
#define BB 2
#define PSTEPS 10
#define NC 8   // B*D columns of the skinny GEMM

// Persistent scratch (fully rewritten every launch -> deterministic)
__device__ __align__(16) float g_win[TT][NN][NC];          // [slot][n][b*4+d]
__device__ __align__(16) float g_PWp[2][TT][EE][NN][NC];   // [half][slot][e][n][c], values x4096
__device__ __align__(16) float g_rsp[2][EE][NN];           // partial row sums (fp32 exact)
__device__ __align__(16) __half g_Ah[(size_t)EE * NN * NN]; // A x4096 in fp16 (100 MB)
__device__ int g_mask[NN];

// ---------------------------------------------------------------------------
// Init: scatter time_segs [B,T,N,D] into window slots; zero mask.
// ---------------------------------------------------------------------------
__global__ void k_init(const float* __restrict__ ts) {
  int i = blockIdx.x * blockDim.x + threadIdx.x;
  if (i < NN) g_mask[i] = 0;
  if (i < BB * TT * NN * DDIM) {
    int d  = i & 3;
    int n  = (i >> 2) & (NN - 1);
    int bt = i >> 14;          // b*5 + t
    int t  = bt % 5;
    int b  = bt / 5;
    g_win[t][n][b * 4 + d] = ts[i];
  }
}

// ---------------------------------------------------------------------------
// Slot-0 GEMM over fp32 A, m-split 2 halves, PLUS (fused in the same stream):
//   - g_Ah = fp16(A * 4096)           (exact pow-2 scale, one-time convert)
//   - exact fp32 per-half row sums
//   - column-any node mask
//   - slot-0 PW partials, scaled x4096 to match the fp16 passes
// block = 128 (4 warps), warp owns 4 rows, lanes split m in float4 quads.
// grid = EE * 512 (e * 2-halves * 256 row-tiles).
// ---------------------------------------------------------------------------
__global__ void __launch_bounds__(128, 6) k_gemm_rs(const float* __restrict__ A) {
  __shared__ __align__(16) float XTs[8 * 512];   // 16 KB, col-major X tile
  __shared__ unsigned s_any[4][128];

  const float* X = &g_win[0][0][0];
  int e     = blockIdx.x / 512;
  int rest  = blockIdx.x & 511;
  int half  = rest >> 8;
  int tile  = rest & 255;
  int mbase = half * 2048;
  int warp  = threadIdx.x >> 5, lane = threadIdx.x & 31;
  int row0  = tile * 16 + warp * 4;

  const float* Ab0 = A + (size_t)e * NN * NN + (size_t)row0 * NN + mbase;
  const float* Ab1 = Ab0 + NN;
  const float* Ab2 = Ab1 + NN;
  const float* Ab3 = Ab2 + NN;
  __half* H0 = g_Ah + (size_t)e * NN * NN + (size_t)row0 * NN + mbase;
  __half* H1 = H0 + NN;
  __half* H2 = H1 + NN;
  __half* H3 = H2 + NN;

  float acc[4][8];
#pragma unroll
  for (int r = 0; r < 4; r++)
#pragma unroll
    for (int c = 0; c < 8; c++) acc[r][c] = 0.f;
  float rs[4] = {0.f, 0.f, 0.f, 0.f};

  for (int t0 = 0; t0 < 2048; t0 += 512) {
    __syncthreads();
    const float4* X4 = (const float4*)(X + (size_t)(mbase + t0) * NC);
    for (int i = threadIdx.x; i < 1024; i += 128) {
      float4 v = X4[i];
      int m = i >> 1, c0 = (i & 1) * 4;
      XTs[(c0 + 0) * 512 + m] = v.x;
      XTs[(c0 + 1) * 512 + m] = v.y;
      XTs[(c0 + 2) * 512 + m] = v.z;
      XTs[(c0 + 3) * 512 + m] = v.w;
    }
    __syncthreads();

    const float4* A0 = (const float4*)(Ab0 + t0);
    const float4* A1 = (const float4*)(Ab1 + t0);
    const float4* A2 = (const float4*)(Ab2 + t0);
    const float4* A3 = (const float4*)(Ab3 + t0);

#pragma unroll 2
    for (int it = 0; it < 4; it++) {
      int mq = it * 32 + lane;
      float4 a0 = __ldcs(A0 + mq);
      float4 a1 = __ldcs(A1 + mq);
      float4 a2 = __ldcs(A2 + mq);
      float4 a3 = __ldcs(A3 + mq);

      // fused fp16 conversion (x4096) -- one uint2 (8B) store per row
      {
        __half2 h01, h23;
        uint2 pk;
        h01 = __floats2half2_rn(a0.x * 4096.f, a0.y * 4096.f);
        h23 = __floats2half2_rn(a0.z * 4096.f, a0.w * 4096.f);
        pk.x = *(unsigned*)&h01; pk.y = *(unsigned*)&h23;
        *(uint2*)(H0 + t0 + 4 * mq) = pk;
        h01 = __floats2half2_rn(a1.x * 4096.f, a1.y * 4096.f);
        h23 = __floats2half2_rn(a1.z * 4096.f, a1.w * 4096.f);
        pk.x = *(unsigned*)&h01; pk.y = *(unsigned*)&h23;
        *(uint2*)(H1 + t0 + 4 * mq) = pk;
        h01 = __floats2half2_rn(a2.x * 4096.f, a2.y * 4096.f);
        h23 = __floats2half2_rn(a2.z * 4096.f, a2.w * 4096.f);
        pk.x = *(unsigned*)&h01; pk.y = *(unsigned*)&h23;
        *(uint2*)(H2 + t0 + 4 * mq) = pk;
        h01 = __floats2half2_rn(a3.x * 4096.f, a3.y * 4096.f);
        h23 = __floats2half2_rn(a3.z * 4096.f, a3.w * 4096.f);
        pk.x = *(unsigned*)&h01; pk.y = *(unsigned*)&h23;
        *(uint2*)(H3 + t0 + 4 * mq) = pk;
      }

      rs[0] += (a0.x + a0.y) + (a0.z + a0.w);
      rs[1] += (a1.x + a1.y) + (a1.z + a1.w);
      rs[2] += (a2.x + a2.y) + (a2.z + a2.w);
      rs[3] += (a3.x + a3.y) + (a3.z + a3.w);
      unsigned v = 0;
      if (a0.x > 0.f || a1.x > 0.f || a2.x > 0.f || a3.x > 0.f) v |= 0x1u;
      if (a0.y > 0.f || a1.y > 0.f || a2.y > 0.f || a3.y > 0.f) v |= 0x100u;
      if (a0.z > 0.f || a1.z > 0.f || a2.z > 0.f || a3.z > 0.f) v |= 0x10000u;
      if (a0.w > 0.f || a1.w > 0.f || a2.w > 0.f || a3.w > 0.f) v |= 0x1000000u;
      s_any[warp][mq] = v;   // every warp covers every mq of the tile

#pragma unroll
      for (int c = 0; c < 8; c++) {
        const float4 x = *(const float4*)&XTs[c * 512 + 4 * mq];
        acc[0][c] = fmaf(a0.w, x.w, fmaf(a0.z, x.z, fmaf(a0.y, x.y, fmaf(a0.x, x.x, acc[0][c]))));
        acc[1][c] = fmaf(a1.w, x.w, fmaf(a1.z, x.z, fmaf(a1.y, x.y, fmaf(a1.x, x.x, acc[1][c]))));
        acc[2][c] = fmaf(a2.w, x.w, fmaf(a2.z, x.z, fmaf(a2.y, x.y, fmaf(a2.x, x.x, acc[2][c]))));
        acc[3][c] = fmaf(a3.w, x.w, fmaf(a3.z, x.z, fmaf(a3.y, x.y, fmaf(a3.x, x.x, acc[3][c]))));
      }
    }

    __syncthreads();
    for (int i = threadIdx.x; i < 128; i += 128) {
      unsigned v = s_any[0][i] | s_any[1][i] | s_any[2][i] | s_any[3][i];
      int mg = mbase + t0 + i * 4;
      if (v & 0x1u)        g_mask[mg + 0] = 1;   // same-value store: race-safe
      if (v & 0x100u)      g_mask[mg + 1] = 1;
      if (v & 0x10000u)    g_mask[mg + 2] = 1;
      if (v & 0x1000000u)  g_mask[mg + 3] = 1;
    }
  }

  // deterministic butterfly reduction across lanes
#pragma unroll
  for (int r = 0; r < 4; r++) {
#pragma unroll
    for (int c = 0; c < 8; c++) {
      float v = acc[r][c];
#pragma unroll
      for (int off = 16; off; off >>= 1) v += __shfl_xor_sync(0xffffffffu, v, off);
      acc[r][c] = v;
    }
    float v = rs[r];
#pragma unroll
    for (int off = 16; off; off >>= 1) v += __shfl_xor_sync(0xffffffffu, v, off);
    rs[r] = v;
  }
  if (lane == 0) {
#pragma unroll
    for (int r = 0; r < 4; r++) {
      float4* dst = (float4*)&g_PWp[half][0][e][row0 + r][0];
      dst[0] = make_float4(acc[r][0] * 4096.f, acc[r][1] * 4096.f,
                           acc[r][2] * 4096.f, acc[r][3] * 4096.f);
      dst[1] = make_float4(acc[r][4] * 4096.f, acc[r][5] * 4096.f,
                           acc[r][6] * 4096.f, acc[r][7] * 4096.f);
      g_rsp[half][e][row0 + r] = rs[r];
    }
  }
}

// ---------------------------------------------------------------------------
// fp16-A tall-skinny GEMM (half the stream bytes). Same shape as k_gemm_rs:
// 4 rows/warp, m-split 2 halves, 512-m col-major X tile, conflict-free
// LDS.128 per col. A loads are uint2 (4 halves), converted to fp32 pairs;
// accumulation fp32, deterministic. Results are x4096 (g_Ah scale).
// grid = EE * 512.
// ---------------------------------------------------------------------------
__global__ void __launch_bounds__(128, 6) k_gemm_h(int slot) {
  __shared__ __align__(16) float XTs[8 * 512];   // 16 KB

  const float* X = &g_win[slot][0][0];
  int e     = blockIdx.x / 512;
  int rest  = blockIdx.x & 511;
  int half  = rest >> 8;
  int tile  = rest & 255;
  int mbase = half * 2048;
  int warp  = threadIdx.x >> 5, lane = threadIdx.x & 31;
  int row0  = tile * 16 + warp * 4;

  const __half* Hb0 = g_Ah + (size_t)e * NN * NN + (size_t)row0 * NN + mbase;
  const __half* Hb1 = Hb0 + NN;
  const __half* Hb2 = Hb1 + NN;
  const __half* Hb3 = Hb2 + NN;

  float acc[4][8];
#pragma unroll
  for (int r = 0; r < 4; r++)
#pragma unroll
    for (int c = 0; c < 8; c++) acc[r][c] = 0.f;

  for (int t0 = 0; t0 < 2048; t0 += 512) {
    __syncthreads();
    const float4* X4 = (const float4*)(X + (size_t)(mbase + t0) * NC);
    for (int i = threadIdx.x; i < 1024; i += 128) {
      float4 v = X4[i];
      int m = i >> 1, c0 = (i & 1) * 4;
      XTs[(c0 + 0) * 512 + m] = v.x;
      XTs[(c0 + 1) * 512 + m] = v.y;
      XTs[(c0 + 2) * 512 + m] = v.z;
      XTs[(c0 + 3) * 512 + m] = v.w;
    }
    __syncthreads();

    const uint2* A0 = (const uint2*)(Hb0 + t0);
    const uint2* A1 = (const uint2*)(Hb1 + t0);
    const uint2* A2 = (const uint2*)(Hb2 + t0);
    const uint2* A3 = (const uint2*)(Hb3 + t0);

#pragma unroll 4
    for (int it = 0; it < 4; it++) {
      int mq = it * 32 + lane;
      uint2 u0 = __ldcs(A0 + mq);
      uint2 u1 = __ldcs(A1 + mq);
      uint2 u2 = __ldcs(A2 + mq);
      uint2 u3 = __ldcs(A3 + mq);

      float2 a0lo = __half22float2(*(__half2*)&u0.x);
      float2 a0hi = __half22float2(*(__half2*)&u0.y);
      float2 a1lo = __half22float2(*(__half2*)&u1.x);
      float2 a1hi = __half22float2(*(__half2*)&u1.y);
      float2 a2lo = __half22float2(*(__half2*)&u2.x);
      float2 a2hi = __half22float2(*(__half2*)&u2.y);
      float2 a3lo = __half22float2(*(__half2*)&u3.x);
      float2 a3hi = __half22float2(*(__half2*)&u3.y);

#pragma unroll
      for (int c = 0; c < 8; c++) {
        const float4 x = *(const float4*)&XTs[c * 512 + 4 * mq];
        acc[0][c] = fmaf(a0hi.y, x.w, fmaf(a0hi.x, x.z, fmaf(a0lo.y, x.y, fmaf(a0lo.x, x.x, acc[0][c]))));
        acc[1][c] = fmaf(a1hi.y, x.w, fmaf(a1hi.x, x.z, fmaf(a1lo.y, x.y, fmaf(a1lo.x, x.x, acc[1][c]))));
        acc[2][c] = fmaf(a2hi.y, x.w, fmaf(a2hi.x, x.z, fmaf(a2lo.y, x.y, fmaf(a2lo.x, x.x, acc[2][c]))));
        acc[3][c] = fmaf(a3hi.y, x.w, fmaf(a3hi.x, x.z, fmaf(a3lo.y, x.y, fmaf(a3lo.x, x.x, acc[3][c]))));
      }
    }
  }

  // deterministic butterfly reduction across lanes
#pragma unroll
  for (int r = 0; r < 4; r++)
#pragma unroll
    for (int c = 0; c < 8; c++) {
      float v = acc[r][c];
#pragma unroll
      for (int off = 16; off; off >>= 1) v += __shfl_xor_sync(0xffffffffu, v, off);
      acc[r][c] = v;
    }
  if (lane == 0) {
#pragma unroll
    for (int r = 0; r < 4; r++) {
      float4* dst = (float4*)&g_PWp[half][slot][e][row0 + r][0];
      dst[0] = make_float4(acc[r][0], acc[r][1], acc[r][2], acc[r][3]);
      dst[1] = make_float4(acc[r][4], acc[r][5], acc[r][6], acc[r][7]);
    }
  }
}

// ---------------------------------------------------------------------------
// Fused per-node step. block = 128 (4 warps), each warp handles 4 (b,n)
// instances; lane owns channels {2l, 2l+1}. Encoder weights staged in smem
// in 32-f chunks. PW partials are x4096 -> unscale by 2^-12 at staging.
// grid = 512.
// ---------------------------------------------------------------------------
__global__ void __launch_bounds__(128) k_step(
    const float* __restrict__ conv_w, const float* __restrict__ conv_b,
    const float* __restrict__ enc_w1, const float* __restrict__ enc_w2,
    const float* __restrict__ enc_b,  const float* __restrict__ dec_w,
    const float* __restrict__ dec_b,  const float* __restrict__ out_w,
    const float* __restrict__ out_b,  float* __restrict__ dout, int s)
{
  __shared__ __align__(16) float s_win[4][4][20];
  __shared__ __align__(16) float s_pw [4][4][60];
  __shared__ __align__(16) float s_cond[4][4][64];
  __shared__ __align__(16) float s_agg [4][4][192];
  __shared__ __align__(16) float s_enc [4][4][64];
  __shared__ __align__(16) float4 s_ew[32][32];   // 16 KB chunk of enc weights

  int warp = threadIdx.x >> 5, lane = threadIdx.x & 31;
  int l2 = lane * 2;
  int base = blockIdx.x * 16 + warp * 4;
  const float kInv = 0x1p-12f;   // 1/4096

  // ---- stage window + PW (sum of m-halves, unscaled) ----
  for (int j = lane; j < 80; j += 32) {
    int li = j / 20, k = j % 20;
    int inst = base + li;
    int b = inst >> 12, n = inst & (NN - 1);
    if (k < 5) {
      int slotv = (s + k) % 5;
      float4 v = *(const float4*)&g_win[slotv][n][b * 4];
      *(float4*)&s_win[warp][li][k * 4] = v;
    } else {
      int k2 = k - 5, e = k2 / 5, t = k2 % 5;
      int slotv = (s + t) % 5;
      float4 v0 = *(const float4*)&g_PWp[0][slotv][e][n][b * 4];
      float4 v1 = *(const float4*)&g_PWp[1][slotv][e][n][b * 4];
      *(float4*)&s_pw[warp][li][e * 20 + t * 4] =
          make_float4((v0.x + v1.x) * kInv, (v0.y + v1.y) * kInv,
                      (v0.z + v1.z) * kInv, (v0.w + v1.w) * kInv);
    }
  }
  __syncwarp();

  int nn[4];
#pragma unroll
  for (int i = 0; i < 4; i++) nn[i] = (base + i) & (NN - 1);

  // ---- cond + agg (20 -> 64 contractions) ----
  float2 cb = *(const float2*)&conv_b[l2];
  float cond[4][2], agg[4][3][2];
#pragma unroll
  for (int i = 0; i < 4; i++) {
    cond[i][0] = cb.x; cond[i][1] = cb.y;
#pragma unroll
    for (int e = 0; e < 3; e++) {
      float r = g_rsp[0][e][nn[i]] + g_rsp[1][e][nn[i]];
      agg[i][e][0] = r * cb.x; agg[i][e][1] = r * cb.y;
    }
  }
  for (int td = 0; td < 20; td++) {
    float2 cw = *(const float2*)&conv_w[td * 64 + l2];
#pragma unroll
    for (int i = 0; i < 4; i++) {
      float w = s_win[warp][i][td];
      cond[i][0] += w * cw.x; cond[i][1] += w * cw.y;
#pragma unroll
      for (int e = 0; e < 3; e++) {
        float a = s_pw[warp][i][e * 20 + td];
        agg[i][e][0] += a * cw.x; agg[i][e][1] += a * cw.y;
      }
    }
  }
#pragma unroll
  for (int i = 0; i < 4; i++) {
    *(float2*)&s_cond[warp][i][l2] = make_float2(cond[i][0], cond[i][1]);
#pragma unroll
    for (int e = 0; e < 3; e++)
      *(float2*)&s_agg[warp][i][e * 64 + l2] = make_float2(agg[i][e][0], agg[i][e][1]);
  }
  __syncthreads();

  // ---- per-edge-type GCSConv + tanh stack (smem-staged weights) ----
  float encs[4][2];
#pragma unroll
  for (int i = 0; i < 4; i++) { encs[i][0] = 0.f; encs[i][1] = 0.f; }
  for (int e = 0; e < 3; e++) {
    float acc[4][2];
    float2 eb = *(const float2*)&enc_b[e * 64 + l2];
#pragma unroll
    for (int i = 0; i < 4; i++) { acc[i][0] = eb.x; acc[i][1] = eb.y; }
    for (int fc = 0; fc < 2; fc++) {
      for (int i2 = threadIdx.x; i2 < 1024; i2 += 128) {
        int f = i2 >> 5, p = i2 & 31;
        int row = (e * 64 + fc * 32 + f) * 64 + 2 * p;
        float2 w1 = *(const float2*)&enc_w1[row];
        float2 w2 = *(const float2*)&enc_w2[row];
        s_ew[f][p] = make_float4(w1.x, w1.y, w2.x, w2.y);
      }
      __syncthreads();
#pragma unroll 8
      for (int f = 0; f < 32; f++) {
        float4 w = s_ew[f][lane];
#pragma unroll
        for (int i = 0; i < 4; i++) {
          float a = s_agg[warp][i][e * 64 + fc * 32 + f];
          float c = s_cond[warp][i][fc * 32 + f];
          acc[i][0] += a * w.x + c * w.z;
          acc[i][1] += a * w.y + c * w.w;
        }
      }
      __syncthreads();
    }
#pragma unroll
    for (int i = 0; i < 4; i++) {
      encs[i][0] += tanhf(acc[i][0]);
      encs[i][1] += tanhf(acc[i][1]);
    }
  }
#pragma unroll
  for (int i = 0; i < 4; i++) {
    float mk = g_mask[nn[i]] ? 1.0f : 0.0f;
    *(float2*)&s_enc[warp][i][l2] =
        make_float2(tanhf(encs[i][0]) * mk, tanhf(encs[i][1]) * mk);
  }
  __syncwarp();

  // ---- decoder: relu([cond, enc] @ dec_w + dec_b) ----
  float hh[4][2];
  float2 db = *(const float2*)&dec_b[l2];
#pragma unroll
  for (int i = 0; i < 4; i++) { hh[i][0] = db.x; hh[i][1] = db.y; }
  for (int k = 0; k < 64; k++) {
    float2 dw = *(const float2*)&dec_w[k * 64 + l2];
#pragma unroll
    for (int i = 0; i < 4; i++) {
      float x = s_cond[warp][i][k];
      hh[i][0] += x * dw.x; hh[i][1] += x * dw.y;
    }
  }
  for (int k = 0; k < 64; k++) {
    float2 dw = *(const float2*)&dec_w[(64 + k) * 64 + l2];
#pragma unroll
    for (int i = 0; i < 4; i++) {
      float x = s_enc[warp][i][k];
      hh[i][0] += x * dw.x; hh[i][1] += x * dw.y;
    }
  }
#pragma unroll
  for (int i = 0; i < 4; i++) {
    hh[i][0] = fmaxf(hh[i][0], 0.f);
    hh[i][1] = fmaxf(hh[i][1], 0.f);
  }

  // ---- output projection + residual + window update ----
  float4 owa = *(const float4*)&out_w[l2 * 4];
  float4 owb = *(const float4*)&out_w[(l2 + 1) * 4];
  float ob0 = out_b[0], ob1 = out_b[1], ob2 = out_b[2], ob3 = out_b[3];
  int slot_new = s % 5;
#pragma unroll
  for (int i = 0; i < 4; i++) {
    float p0 = hh[i][0] * owa.x + hh[i][1] * owb.x;
    float p1 = hh[i][0] * owa.y + hh[i][1] * owb.y;
    float p2 = hh[i][0] * owa.z + hh[i][1] * owb.z;
    float p3 = hh[i][0] * owa.w + hh[i][1] * owb.w;
#pragma unroll
    for (int off = 16; off; off >>= 1) {
      p0 += __shfl_xor_sync(0xffffffffu, p0, off);
      p1 += __shfl_xor_sync(0xffffffffu, p1, off);
      p2 += __shfl_xor_sync(0xffffffffu, p2, off);
      p3 += __shfl_xor_sync(0xffffffffu, p3, off);
    }
    if (lane == 0) {
      int inst = base + i;
      int b = inst >> 12, n = inst & (NN - 1);
      float4 o;
      o.x = s_win[warp][i][16] + tanhf(p0 + ob0);
      o.y = s_win[warp][i][17] + tanhf(p1 + ob1);
      o.z = s_win[warp][i][18] + tanhf(p2 + ob2);
      o.w = s_win[warp][i][19] + tanhf(p3 + ob3);
      *(float4*)&g_win[slot_new][n][b * 4] = o;
      *(float4*)&dout[(size_t)((b * PSTEPS + s) * NN + n) * 4] = o;
    }
  }
}

// ---------------------------------------------------------------------------
extern "C" void kernel_launch(void* const* d_in, const int* in_sizes, int n_in,
                              void* d_out, int out_size) {
  const float* ts     = (const float*)d_in[0];
  const float* A      = (const float*)d_in[1];
  const float* conv_w = (const float*)d_in[2];
  const float* conv_b = (const float*)d_in[3];
  const float* enc_w1 = (const float*)d_in[4];
  const float* enc_w2 = (const float*)d_in[5];
  const float* enc_b  = (const float*)d_in[6];
  const float* dec_w  = (const float*)d_in[7];
  const float* dec_b  = (const float*)d_in[8];
  const float* out_w  = (const float*)d_in[9];
  const float* out_b  = (const float*)d_in[10];
  float* out = (float*)d_out;

  k_init<<<640, 256>>>(ts);
  k_gemm_rs<<<EE * 512, 128>>>(A);          // slot0 PW + rowsums + mask + Ah
  for (int t = 1; t < TT; t++)
    k_gemm_h<<<EE * 512, 128>>>(t);         // fp16 stream (100 MB/pass)

  for (int s = 0; s < PSTEPS; s++) {
    k_step<<<512, 128>>>(conv_w, conv_b, enc_w1, enc_w2, enc_b,
                         dec_w, dec_b, out_w, out_b, out, s);
    if (s < PSTEPS - 1)
      k_gemm_h<<<EE * 512, 128>>>(s % 5);
  }
}